// round 1
// baseline (speedup 1.0000x reference)
#include <cuda_runtime.h>

#define N_NODES 100000
#define IN_DIM  512
#define HIDDEN  16
#define OUT_DIM 64

// Scratch (device globals — allocation-free per harness rules)
__device__ float g_deg [N_NODES];
__device__ float g_dinv[N_NODES];
__device__ float g_hs1 [N_NODES * HIDDEN];   // (x@W1) * dinv[node]
__device__ float g_acc1[N_NODES * HIDDEN];   // scatter accumulator layer 1
__device__ float g_zs  [N_NODES * HIDDEN];   // relu(...) * dinv[node]
__device__ float g_acc2[N_NODES * HIDDEN];   // scatter accumulator layer 2

// ---------------------------------------------------------------------------
__global__ void k_zero() {
    int stride = gridDim.x * blockDim.x;
    int i = blockIdx.x * blockDim.x + threadIdx.x;
    for (int j = i; j < N_NODES * HIDDEN; j += stride) {
        g_acc1[j] = 0.f;
        g_acc2[j] = 0.f;
    }
    for (int j = i; j < N_NODES; j += stride) g_deg[j] = 0.f;
}

__global__ void k_degree(const int* __restrict__ dst, int E) {
    int i = blockIdx.x * blockDim.x + threadIdx.x;
    if (i < E) atomicAdd(&g_deg[dst[i]], 1.0f);   // compiles to RED (no return)
}

__global__ void k_dinv() {
    int i = blockIdx.x * blockDim.x + threadIdx.x;
    if (i < N_NODES) g_dinv[i] = rsqrtf(g_deg[i] + 1.0f);   // +1 = self-loop
}

// ---------------------------------------------------------------------------
// GEMM1: hs1[n][f] = (sum_k x[n][k] * W1[k][f]) * dinv[n]
// Block: 256 threads, 64 rows. Thread = 4 rows x 1 feature, float4 over k.
#define G1_ROWS 64
#define G1_KC   32

__global__ __launch_bounds__(256) void k_gemm1(const float* __restrict__ x,
                                               const float* __restrict__ W1) {
    __shared__ float WsT[HIDDEN][IN_DIM + 4];   // transposed W1, pad 4 (2-way max)
    __shared__ float xs[G1_ROWS][G1_KC + 4];    // pad 4: bank shift + 16B align

    int tid = threadIdx.x;
    // Load + transpose W1 (32 KB, once per block)
    for (int j = tid; j < IN_DIM * HIDDEN; j += 256) {
        int k = j >> 4, f = j & 15;
        WsT[f][k] = W1[j];
    }

    int row0 = blockIdx.x * G1_ROWS;
    int f  = tid & 15;
    int rb = (tid >> 4) << 2;          // 0,4,...,60
    float a0 = 0.f, a1 = 0.f, a2 = 0.f, a3 = 0.f;

    const float4* xg = reinterpret_cast<const float4*>(x);

    for (int kc = 0; kc < IN_DIM; kc += G1_KC) {
        __syncthreads();
        // Stage 64 rows x 32 k: 512 float4, 2 per thread, coalesced
        #pragma unroll
        for (int l = 0; l < 2; l++) {
            int idx = tid + l * 256;          // 0..511
            int rr = idx >> 3;                // 0..63
            int cc = idx & 7;                 // float4 col 0..7
            int grow = row0 + rr;
            if (grow >= N_NODES) grow = N_NODES - 1;   // clamp (last block)
            float4 v = xg[(size_t)grow * (IN_DIM / 4) + (kc >> 2) + cc];
            *reinterpret_cast<float4*>(&xs[rr][cc * 4]) = v;
        }
        __syncthreads();

        #pragma unroll
        for (int k4 = 0; k4 < G1_KC; k4 += 4) {
            float4 w = *reinterpret_cast<const float4*>(&WsT[f][kc + k4]);
            float4 r0 = *reinterpret_cast<const float4*>(&xs[rb + 0][k4]);
            float4 r1 = *reinterpret_cast<const float4*>(&xs[rb + 1][k4]);
            float4 r2 = *reinterpret_cast<const float4*>(&xs[rb + 2][k4]);
            float4 r3 = *reinterpret_cast<const float4*>(&xs[rb + 3][k4]);
            a0 = fmaf(r0.x, w.x, a0); a0 = fmaf(r0.y, w.y, a0);
            a0 = fmaf(r0.z, w.z, a0); a0 = fmaf(r0.w, w.w, a0);
            a1 = fmaf(r1.x, w.x, a1); a1 = fmaf(r1.y, w.y, a1);
            a1 = fmaf(r1.z, w.z, a1); a1 = fmaf(r1.w, w.w, a1);
            a2 = fmaf(r2.x, w.x, a2); a2 = fmaf(r2.y, w.y, a2);
            a2 = fmaf(r2.z, w.z, a2); a2 = fmaf(r2.w, w.w, a2);
            a3 = fmaf(r3.x, w.x, a3); a3 = fmaf(r3.y, w.y, a3);
            a3 = fmaf(r3.z, w.z, a3); a3 = fmaf(r3.w, w.w, a3);
        }
    }

    int r = row0 + rb;
    if (r + 0 < N_NODES) g_hs1[(r + 0) * HIDDEN + f] = a0 * g_dinv[r + 0];
    if (r + 1 < N_NODES) g_hs1[(r + 1) * HIDDEN + f] = a1 * g_dinv[r + 1];
    if (r + 2 < N_NODES) g_hs1[(r + 2) * HIDDEN + f] = a2 * g_dinv[r + 2];
    if (r + 3 < N_NODES) g_hs1[(r + 3) * HIDDEN + f] = a3 * g_dinv[r + 3];
}

// ---------------------------------------------------------------------------
// Edge scatter: acc[dst] += table[src] (16 floats), via red.global.add.v4.f32
__device__ __forceinline__ void red_add_v4(float* p, float4 v) {
    asm volatile("red.global.add.v4.f32 [%0], {%1,%2,%3,%4};"
                 :: "l"(p), "f"(v.x), "f"(v.y), "f"(v.z), "f"(v.w) : "memory");
}

__global__ void k_scatter(const int* __restrict__ src, const int* __restrict__ dst,
                          int E, int phase) {
    int e = blockIdx.x * blockDim.x + threadIdx.x;
    if (e >= E) return;
    const float* tab = phase ? g_zs  : g_hs1;
    float*       acc = phase ? g_acc2 : g_acc1;
    int s = __ldg(src + e);
    int d = __ldg(dst + e);
    const float4* tv = reinterpret_cast<const float4*>(tab + (size_t)s * HIDDEN);
    float4 v0 = tv[0], v1 = tv[1], v2 = tv[2], v3 = tv[3];
    float* p = acc + (size_t)d * HIDDEN;
    red_add_v4(p +  0, v0);
    red_add_v4(p +  4, v1);
    red_add_v4(p +  8, v2);
    red_add_v4(p + 12, v3);
}

// ---------------------------------------------------------------------------
// Layer-1 epilogue: z = relu(dinv*(acc1 + hs1) + b1); zs = z * dinv
__global__ void k_mid(const float* __restrict__ b1) {
    int i = blockIdx.x * blockDim.x + threadIdx.x;
    if (i >= N_NODES * HIDDEN) return;
    int node = i >> 4, f = i & 15;
    float dv = g_dinv[node];
    float v  = fmaf(dv, g_acc1[i] + g_hs1[i], b1[f]);
    v = fmaxf(v, 0.f);
    g_zs[i] = v * dv;
}

// ---------------------------------------------------------------------------
// Final: agg[d] = dinv[d]*(acc2[d] + zs[d]);  out[d] = agg @ W2 + b2
// Block: 256 threads = 4 nodes x 64 output features.
__global__ __launch_bounds__(256) void k_final(const float* __restrict__ W2,
                                               const float* __restrict__ b2,
                                               float* __restrict__ out) {
    __shared__ float W2s[HIDDEN * OUT_DIM];   // 4 KB
    __shared__ float aggs[4][HIDDEN];
    int tid = threadIdx.x;
    for (int j = tid; j < HIDDEN * OUT_DIM; j += 256) W2s[j] = W2[j];

    int n = tid >> 6;          // node within block: 0..3
    int o = tid & 63;          // output feature
    int node = blockIdx.x * 4 + n;

    if (o < HIDDEN) {
        float dv = g_dinv[node];
        int idx = node * HIDDEN + o;
        aggs[n][o] = dv * (g_acc2[idx] + g_zs[idx]);
    }
    __syncthreads();

    float acc = b2[o];
    #pragma unroll
    for (int k = 0; k < HIDDEN; k++)
        acc = fmaf(aggs[n][k], W2s[k * OUT_DIM + o], acc);
    out[(size_t)node * OUT_DIM + o] = acc;
}

// ---------------------------------------------------------------------------
extern "C" void kernel_launch(void* const* d_in, const int* in_sizes, int n_in,
                              void* d_out, int out_size) {
    const float* x  = (const float*)d_in[0];
    const float* W1 = (const float*)d_in[1];
    const float* b1 = (const float*)d_in[2];
    const float* W2 = (const float*)d_in[3];
    const float* b2 = (const float*)d_in[4];
    const int*   ei = (const int*)d_in[5];
    float* out = (float*)d_out;

    int E = in_sizes[5] / 2;
    const int* src = ei;       // edge_index[0]
    const int* dst = ei + E;   // edge_index[1]

    k_zero  <<<1024, 256>>>();
    k_degree<<<(E + 255) / 256, 256>>>(dst, E);
    k_dinv  <<<(N_NODES + 255) / 256, 256>>>();
    k_gemm1 <<<(N_NODES + G1_ROWS - 1) / G1_ROWS, 256>>>(x, W1);
    k_scatter<<<(E + 255) / 256, 256>>>(src, dst, E, 0);
    k_mid   <<<(N_NODES * HIDDEN + 255) / 256, 256>>>(b1);
    k_scatter<<<(E + 255) / 256, 256>>>(src, dst, E, 1);
    k_final <<<N_NODES / 4, 256>>>(W2, b2, out);
}

// round 2
// speedup vs baseline: 1.3591x; 1.3591x over previous
#include <cuda_runtime.h>

#define N_NODES 100000
#define IN_DIM  512
#define HIDDEN  16
#define OUT_DIM 64

// Scratch (device globals — allocation-free per harness rules)
__device__ float g_deg [N_NODES];
__device__ float g_dinv[N_NODES];
__device__ float g_hs1 [N_NODES * HIDDEN];   // (x@W1) * dinv[node]
__device__ float g_acc1[N_NODES * HIDDEN];   // scatter accumulator layer 1
__device__ float g_zs  [N_NODES * HIDDEN];   // relu(...) * dinv[node]
__device__ float g_acc2[N_NODES * HIDDEN];   // scatter accumulator layer 2

// ---------------------------------------------------------------------------
__global__ void k_zero() {
    int stride = gridDim.x * blockDim.x;
    int i = blockIdx.x * blockDim.x + threadIdx.x;
    for (int j = i; j < N_NODES * HIDDEN; j += stride) {
        g_acc1[j] = 0.f;
        g_acc2[j] = 0.f;
    }
    for (int j = i; j < N_NODES; j += stride) g_deg[j] = 0.f;
}

__global__ void k_degree(const int* __restrict__ dst, int E) {
    int i = blockIdx.x * blockDim.x + threadIdx.x;
    if (i < E) atomicAdd(&g_deg[dst[i]], 1.0f);   // compiles to RED
}

__global__ void k_dinv() {
    int i = blockIdx.x * blockDim.x + threadIdx.x;
    if (i < N_NODES) g_dinv[i] = rsqrtf(g_deg[i] + 1.0f);   // +1 = self-loop
}

// ---------------------------------------------------------------------------
// GEMM1: hs1[n][f] = (sum_k x[n][k] * W1[k][f]) * dinv[n]
// Block: 256 threads, 256 rows. Thread = 4 rows (stride 64) x 4 features.
// x staged in smem (KC=32 chunks); W1 read via __ldg (32KB, L1-resident).
#define G1_ROWS 256
#define G1_KC   32
#define XS_STR  36          // row stride in floats (pad 4: conflict-free pattern)

__global__ __launch_bounds__(256) void k_gemm1(const float* __restrict__ x,
                                               const float* __restrict__ W1) {
    __shared__ float xs[G1_ROWS * XS_STR];    // 36864 B

    int tid = threadIdx.x;
    int fg  = (tid & 3) << 2;                 // feature group: 0,4,8,12
    int rg  = tid >> 2;                       // row group: 0..63
    int row0 = blockIdx.x * G1_ROWS;

    const float4* xg = reinterpret_cast<const float4*>(x);
    const float4* W4 = reinterpret_cast<const float4*>(W1);   // W1[k][f] -> W4[k*4 + f/4]

    float acc[4][4];
    #pragma unroll
    for (int i = 0; i < 4; i++)
        #pragma unroll
        for (int j = 0; j < 4; j++) acc[i][j] = 0.f;

    for (int kc = 0; kc < IN_DIM; kc += G1_KC) {
        __syncthreads();
        // Stage 256 rows x 32 k = 2048 float4, 8 per thread, coalesced
        #pragma unroll
        for (int l = 0; l < 8; l++) {
            int idx = tid + l * 256;          // 0..2047
            int rr = idx >> 3;                // 0..255
            int cc = idx & 7;                 // float4 col 0..7
            int grow = row0 + rr;
            if (grow >= N_NODES) grow = N_NODES - 1;   // clamp (tail block)
            float4 v = xg[(size_t)grow * (IN_DIM / 4) + (kc >> 2) + cc];
            *reinterpret_cast<float4*>(&xs[rr * XS_STR + cc * 4]) = v;
        }
        __syncthreads();

        #pragma unroll
        for (int kk = 0; kk < G1_KC; kk += 4) {
            float4 xv[4];
            #pragma unroll
            for (int i = 0; i < 4; i++)
                xv[i] = *reinterpret_cast<const float4*>(&xs[(rg + i * 64) * XS_STR + kk]);
            #pragma unroll
            for (int j = 0; j < 4; j++) {
                float4 w = __ldg(&W4[(kc + kk + j) * 4 + (fg >> 2)]);
                #pragma unroll
                for (int i = 0; i < 4; i++) {
                    float xj = reinterpret_cast<const float*>(&xv[i])[j];
                    acc[i][0] = fmaf(xj, w.x, acc[i][0]);
                    acc[i][1] = fmaf(xj, w.y, acc[i][1]);
                    acc[i][2] = fmaf(xj, w.z, acc[i][2]);
                    acc[i][3] = fmaf(xj, w.w, acc[i][3]);
                }
            }
        }
    }

    #pragma unroll
    for (int i = 0; i < 4; i++) {
        int r = row0 + rg + i * 64;
        if (r < N_NODES) {
            float dv = g_dinv[r];
            float4 o = make_float4(acc[i][0] * dv, acc[i][1] * dv,
                                   acc[i][2] * dv, acc[i][3] * dv);
            *reinterpret_cast<float4*>(&g_hs1[r * HIDDEN + fg]) = o;
        }
    }
}

// ---------------------------------------------------------------------------
// Edge scatter: acc[dst] += table[src] (16 floats), 4 threads per edge.
__device__ __forceinline__ void red_add_v4(float* p, float4 v) {
    asm volatile("red.global.add.v4.f32 [%0], {%1,%2,%3,%4};"
                 :: "l"(p), "f"(v.x), "f"(v.y), "f"(v.z), "f"(v.w) : "memory");
}

__global__ void k_scatter(const int* __restrict__ src, const int* __restrict__ dst,
                          int E, int phase) {
    int g = blockIdx.x * blockDim.x + threadIdx.x;
    int e = g >> 2;
    if (e >= E) return;
    int q = (g & 3) << 2;
    const float* tab = phase ? g_zs   : g_hs1;
    float*       acc = phase ? g_acc2 : g_acc1;
    int s = __ldg(src + e);
    int d = __ldg(dst + e);
    float4 v = *reinterpret_cast<const float4*>(tab + (size_t)s * HIDDEN + q);
    red_add_v4(acc + (size_t)d * HIDDEN + q, v);
}

// ---------------------------------------------------------------------------
// Layer-1 epilogue: z = relu(dinv*(acc1 + hs1) + b1); zs = z * dinv
__global__ void k_mid(const float* __restrict__ b1) {
    int i = blockIdx.x * blockDim.x + threadIdx.x;
    if (i >= N_NODES * HIDDEN) return;
    int node = i >> 4, f = i & 15;
    float dv = g_dinv[node];
    float v  = fmaf(dv, g_acc1[i] + g_hs1[i], b1[f]);
    v = fmaxf(v, 0.f);
    g_zs[i] = v * dv;
}

// ---------------------------------------------------------------------------
// Final: agg[d] = dinv[d]*(acc2[d] + zs[d]);  out[d] = agg @ W2 + b2
__global__ __launch_bounds__(256) void k_final(const float* __restrict__ W2,
                                               const float* __restrict__ b2,
                                               float* __restrict__ out) {
    __shared__ float W2s[HIDDEN * OUT_DIM];   // 4 KB
    __shared__ float aggs[4][HIDDEN];
    int tid = threadIdx.x;
    for (int j = tid; j < HIDDEN * OUT_DIM; j += 256) W2s[j] = W2[j];

    int n = tid >> 6;          // node within block: 0..3
    int o = tid & 63;          // output feature
    int node = blockIdx.x * 4 + n;

    if (o < HIDDEN) {
        float dv = g_dinv[node];
        int idx = node * HIDDEN + o;
        aggs[n][o] = dv * (g_acc2[idx] + g_zs[idx]);
    }
    __syncthreads();

    float acc = b2[o];
    #pragma unroll
    for (int k = 0; k < HIDDEN; k++)
        acc = fmaf(aggs[n][k], W2s[k * OUT_DIM + o], acc);
    out[(size_t)node * OUT_DIM + o] = acc;
}

// ---------------------------------------------------------------------------
extern "C" void kernel_launch(void* const* d_in, const int* in_sizes, int n_in,
                              void* d_out, int out_size) {
    const float* x  = (const float*)d_in[0];
    const float* W1 = (const float*)d_in[1];
    const float* b1 = (const float*)d_in[2];
    const float* W2 = (const float*)d_in[3];
    const float* b2 = (const float*)d_in[4];
    const int*   ei = (const int*)d_in[5];
    float* out = (float*)d_out;

    int E = in_sizes[5] / 2;
    const int* src = ei;       // edge_index[0]
    const int* dst = ei + E;   // edge_index[1]

    k_zero  <<<1024, 256>>>();
    k_degree<<<(E + 255) / 256, 256>>>(dst, E);
    k_dinv  <<<(N_NODES + 255) / 256, 256>>>();
    k_gemm1 <<<(N_NODES + G1_ROWS - 1) / G1_ROWS, 256>>>(x, W1);
    k_scatter<<<(4 * E + 255) / 256, 256>>>(src, dst, E, 0);
    k_mid   <<<(N_NODES * HIDDEN + 255) / 256, 256>>>(b1);
    k_scatter<<<(4 * E + 255) / 256, 256>>>(src, dst, E, 1);
    k_final <<<N_NODES / 4, 256>>>(W2, b2, out);
}